// round 1
// baseline (speedup 1.0000x reference)
#include <cuda_runtime.h>
#include <math.h>

#define N_NODES 50000
#define N_EDGES 800000
#define NC 4
#define NH 4
#define OUT_F 64
#define J_DIM 1024   // NC*NH*OUT_F

// ---------------- scratch (device globals; no allocations allowed) ----------
__device__ __align__(16) float    g_Wh [(size_t)N_NODES * J_DIM];   // [n][c*256+h*64+o]
__device__ __align__(16) float    g_acc[(size_t)N_NODES * J_DIM];   // scatter accum -> final H per channel
__device__ __align__(16) float    g_el [N_NODES * 16];              // [n][c*4+h]
__device__ __align__(16) float    g_er [N_NODES * 16];
__device__ __align__(16) unsigned g_menc[N_NODES * 16];             // monotonic-encoded segment max
__device__ __align__(16) float    g_den [N_NODES * 16];             // softmax denominators
__device__ __align__(16) float    g_ex  [(size_t)NC * N_EDGES * NH];// per-edge exp values
__device__ int g_mask_mode;                                         // 0=u8, 1=i32, 2=f32

// ---------------- helpers ----------------------------------------------------
__device__ __forceinline__ float warpsum(float v) {
    #pragma unroll
    for (int o = 16; o; o >>= 1) v += __shfl_xor_sync(0xffffffffu, v, o);
    return v;
}
// order-preserving float<->uint encoding for atomicMax on floats
__device__ __forceinline__ unsigned fenc(float f) {
    unsigned u = __float_as_uint(f);
    return (u >> 31) ? ~u : (u | 0x80000000u);
}
__device__ __forceinline__ float fdec(unsigned u) {
    return (u & 0x80000000u) ? __uint_as_float(u ^ 0x80000000u) : __uint_as_float(~u);
}
__device__ __forceinline__ float leaky(float x) { return x > 0.f ? x : 0.2f * x; }

// ---------------- 0. sniff type_mask dtype -----------------------------------
__global__ void detect_kernel(const unsigned char* __restrict__ tm) {
    __shared__ int sawNZ123, sawF32;
    if (threadIdx.x == 0) { sawNZ123 = 0; sawF32 = 0; }
    __syncthreads();
    int nz = 0, f32 = 0;
    for (int i = threadIdx.x; i < 12500; i += blockDim.x) {
        unsigned char b1 = tm[4*i+1], b2 = tm[4*i+2], b3 = tm[4*i+3];
        if (b1 | b2 | b3) nz = 1;
        if (b2 == 0x80 && b3 == 0x3f) f32 = 1;
    }
    if (nz)  atomicOr(&sawNZ123, 1);
    if (f32) atomicOr(&sawF32, 1);
    __syncthreads();
    if (threadIdx.x == 0) g_mask_mode = sawF32 ? 2 : (sawNZ123 ? 0 : 1);
}

// ---------------- 1. init scratch ---------------------------------------------
__global__ void init_kernel() {
    int i = blockIdx.x * 256 + threadIdx.x;                 // 12.8M threads
    if (i < N_NODES * (J_DIM / 4))
        ((float4*)g_acc)[i] = make_float4(0.f, 0.f, 0.f, 0.f);
    if (i < N_NODES * 16) {
        g_menc[i] = 0x007FFFFFu;   // fenc(-inf)
        g_den[i]  = 0.f;
    }
}

// ---------------- 2. projection GEMM: g_Wh[n][j] = sum_k feat[n][k]*Wl[j][k] --
__global__ void gemm_kernel(const float* __restrict__ A, const float* __restrict__ W) {
    __shared__ float As[16][132];   // [k][m], padded
    __shared__ float Bs[16][68];    // [k][j], padded
    const int bm = blockIdx.y * 128;
    const int bn = blockIdx.x * 64;
    const int tid = threadIdx.x;
    const int tm = (tid >> 4) << 3;   // 0..120
    const int tn = (tid & 15) << 2;   // 0..60
    float acc[8][4];
    #pragma unroll
    for (int i = 0; i < 8; i++)
        #pragma unroll
        for (int j = 0; j < 4; j++) acc[i][j] = 0.f;

    for (int k0 = 0; k0 < 256; k0 += 16) {
        #pragma unroll
        for (int it = 0; it < 2; ++it) {
            int l = tid + it * 256;
            int row = l >> 2, seg = l & 3;
            int grow = bm + row; if (grow >= N_NODES) grow = N_NODES - 1;
            float4 v = *(const float4*)&A[(size_t)grow * 256 + k0 + seg * 4];
            As[seg*4+0][row] = v.x; As[seg*4+1][row] = v.y;
            As[seg*4+2][row] = v.z; As[seg*4+3][row] = v.w;
        }
        {
            int j = tid >> 2, seg = tid & 3;
            float4 v = *(const float4*)&W[(size_t)(bn + j) * 256 + k0 + seg * 4];
            Bs[seg*4+0][j] = v.x; Bs[seg*4+1][j] = v.y;
            Bs[seg*4+2][j] = v.z; Bs[seg*4+3][j] = v.w;
        }
        __syncthreads();
        #pragma unroll
        for (int k = 0; k < 16; k++) {
            float4 a0 = *(const float4*)&As[k][tm];
            float4 a1 = *(const float4*)&As[k][tm + 4];
            float4 b  = *(const float4*)&Bs[k][tn];
            float av[8] = {a0.x,a0.y,a0.z,a0.w,a1.x,a1.y,a1.z,a1.w};
            float bv[4] = {b.x,b.y,b.z,b.w};
            #pragma unroll
            for (int i = 0; i < 8; i++)
                #pragma unroll
                for (int j = 0; j < 4; j++)
                    acc[i][j] += av[i] * bv[j];
        }
        __syncthreads();
    }
    #pragma unroll
    for (int i = 0; i < 8; i++) {
        int grow = bm + tm + i;
        if (grow < N_NODES) {
            float4 v = make_float4(acc[i][0], acc[i][1], acc[i][2], acc[i][3]);
            *(float4*)&g_Wh[(size_t)grow * J_DIM + bn + tn] = v;
        }
    }
}

// ---------------- 3. attention coefficients el/er ------------------------------
__global__ void attn_coef_kernel(const float* __restrict__ a_src, const float* __restrict__ a_dst) {
    int wid  = (blockIdx.x * blockDim.x + threadIdx.x) >> 5;   // 0..800000
    int lane = threadIdx.x & 31;
    if (wid >= N_NODES * 16) return;
    int n = wid >> 4, ch = wid & 15;
    const float* wrow = g_Wh + (size_t)n * J_DIM + ch * 64;
    float w0 = wrow[lane], w1 = wrow[lane + 32];
    float s1 = w0 * __ldg(&a_src[ch*64 + lane]) + w1 * __ldg(&a_src[ch*64 + lane + 32]);
    float s2 = w0 * __ldg(&a_dst[ch*64 + lane]) + w1 * __ldg(&a_dst[ch*64 + lane + 32]);
    s1 = warpsum(s1); s2 = warpsum(s2);
    if (lane == 0) { g_el[wid] = s1; g_er[wid] = s2; }
}

// ---------------- 4. segment max over dst neighborhoods ------------------------
__global__ void edge_max_kernel(const int* __restrict__ src, const int* __restrict__ dst) {
    int idx = blockIdx.x * blockDim.x + threadIdx.x;
    if (idx >= NC * N_EDGES) return;
    int c = idx / N_EDGES;
    int s = src[idx], d = dst[idx];
    float4 elv = *(const float4*)&g_el[s * 16 + c * 4];
    float4 erv = *(const float4*)&g_er[d * 16 + c * 4];
    float vx[4] = {elv.x+erv.x, elv.y+erv.y, elv.z+erv.z, elv.w+erv.w};
    #pragma unroll
    for (int h = 0; h < 4; h++)
        atomicMax(&g_menc[d * 16 + c * 4 + h], fenc(leaky(vx[h])));
}

// ---------------- 5. exp + denominator sums ------------------------------------
__global__ void edge_expsum_kernel(const int* __restrict__ src, const int* __restrict__ dst) {
    int idx = blockIdx.x * blockDim.x + threadIdx.x;
    if (idx >= NC * N_EDGES) return;
    int c = idx / N_EDGES;
    int s = src[idx], d = dst[idx];
    float4 elv = *(const float4*)&g_el[s * 16 + c * 4];
    float4 erv = *(const float4*)&g_er[d * 16 + c * 4];
    float vx[4] = {elv.x+erv.x, elv.y+erv.y, elv.z+erv.z, elv.w+erv.w};
    float exv[4];
    #pragma unroll
    for (int h = 0; h < 4; h++) {
        float m = fdec(g_menc[d * 16 + c * 4 + h]);
        float ex = __expf(leaky(vx[h]) - m);
        exv[h] = ex;
        atomicAdd(&g_den[d * 16 + c * 4 + h], ex);
    }
    *(float4*)&g_ex[(size_t)idx * 4] = make_float4(exv[0], exv[1], exv[2], exv[3]);
}

// ---------------- 6. weighted scatter of source features -----------------------
__global__ void scatter_kernel(const int* __restrict__ src, const int* __restrict__ dst) {
    unsigned g = blockIdx.x * 256u + threadIdx.x;      // up to 204.8M
    unsigned ec = g >> 6;
    if (ec >= (unsigned)(NC * N_EDGES)) return;
    int lane = g & 63;
    int c = ec / N_EDGES;
    int s = src[ec], d = dst[ec];
    int h = lane >> 4, q = lane & 15;
    float w = g_ex[(size_t)ec * 4 + h] / g_den[d * 16 + c * 4 + h];
    size_t off = (size_t)c * 256 + h * 64 + q * 4;
    float4 v = *(const float4*)&g_Wh[(size_t)s * J_DIM + off];
    float* ap = &g_acc[(size_t)d * J_DIM + off];
    atomicAdd(ap + 0, w * v.x);
    atomicAdd(ap + 1, w * v.y);
    atomicAdd(ap + 2, w * v.z);
    atomicAdd(ap + 3, w * v.w);
}

// ---------------- 7. residual + bias + elu --------------------------------------
__global__ void finalize_kernel(const float* __restrict__ bias) {
    int i = blockIdx.x * 256 + threadIdx.x;     // over 12.8M float4
    if (i >= N_NODES * (J_DIM / 4)) return;
    int j4 = i & 255;
    float4 a  = ((float4*)g_acc)[i];
    float4 wv = ((const float4*)g_Wh)[i];
    float4 b  = *(const float4*)&bias[j4 * 4];
    float x0 = a.x + wv.x + b.x, x1 = a.y + wv.y + b.y;
    float x2 = a.z + wv.z + b.z, x3 = a.w + wv.w + b.w;
    float4 r;
    r.x = x0 > 0.f ? x0 : expm1f(x0);
    r.y = x1 > 0.f ? x1 : expm1f(x1);
    r.z = x2 > 0.f ? x2 : expm1f(x2);
    r.w = x3 > 0.f ? x3 : expm1f(x3);
    ((float4*)g_acc)[i] = r;
}

// ---------------- 8. channel aggregation + type select --------------------------
__global__ void aggregate_kernel(const void* __restrict__ tm,
                                 const float* __restrict__ Dw, const float* __restrict__ Db,
                                 const float* __restrict__ Ww, const float* __restrict__ Wb,
                                 float* __restrict__ out) {
    int wid  = (blockIdx.x * blockDim.x + threadIdx.x) >> 5;   // node id
    int lane = threadIdx.x & 31;
    if (wid >= N_NODES) return;
    int n = wid;
    const float4* H = (const float4*)(g_acc + (size_t)n * J_DIM);
    float4 v[4][2];
    #pragma unroll
    for (int ch = 0; ch < 4; ch++) {
        v[ch][0] = H[ch * 64 + lane];
        v[ch][1] = H[ch * 64 + lane + 32];
    }
    float dl[2], wl[2];
    #pragma unroll
    for (int r = 0; r < 2; r++) {
        const float4* DwR = (const float4*)(Dw + r * 512);
        const float4* WwR = (const float4*)(Ww + r * 512);
        float4 d0 = DwR[lane], d1 = DwR[lane+32], d2 = DwR[64+lane], d3 = DwR[64+lane+32];
        float4 w0 = WwR[lane], w1 = WwR[lane+32], w2 = WwR[64+lane], w3 = WwR[64+lane+32];
        float sD = v[0][0].x*d0.x + v[0][0].y*d0.y + v[0][0].z*d0.z + v[0][0].w*d0.w
                 + v[0][1].x*d1.x + v[0][1].y*d1.y + v[0][1].z*d1.z + v[0][1].w*d1.w
                 + v[1][0].x*d2.x + v[1][0].y*d2.y + v[1][0].z*d2.z + v[1][0].w*d2.w
                 + v[1][1].x*d3.x + v[1][1].y*d3.y + v[1][1].z*d3.z + v[1][1].w*d3.w;
        float sW = v[2][0].x*w0.x + v[2][0].y*w0.y + v[2][0].z*w0.z + v[2][0].w*w0.w
                 + v[2][1].x*w1.x + v[2][1].y*w1.y + v[2][1].z*w1.z + v[2][1].w*w1.w
                 + v[3][0].x*w2.x + v[3][0].y*w2.y + v[3][0].z*w2.z + v[3][0].w*w2.w
                 + v[3][1].x*w3.x + v[3][1].y*w3.y + v[3][1].z*w3.z + v[3][1].w*w3.w;
        dl[r] = warpsum(sD) + __ldg(&Db[r]);
        wl[r] = warpsum(sW) + __ldg(&Wb[r]);
    }
    float mD = fmaxf(dl[0], dl[1]);
    float e0 = __expf(dl[0] - mD), e1 = __expf(dl[1] - mD);
    float a0 = e0 / (e0 + e1), a1 = e1 / (e0 + e1);
    float mW = fmaxf(wl[0], wl[1]);
    float f0 = __expf(wl[0] - mW), f1 = __expf(wl[1] - mW);
    float b0 = f0 / (f0 + f1), b1 = f1 / (f0 + f1);

    int mode = g_mask_mode;
    bool msk;
    if (mode == 1)      msk = ((const int*)tm)[n] != 0;
    else if (mode == 2) msk = ((const float*)tm)[n] != 0.f;
    else                msk = ((const unsigned char*)tm)[n] != 0;

    float4 r0, r1;
    if (msk) {
        r0.x = v[2][0].x*b0 + v[3][0].x*b1; r0.y = v[2][0].y*b0 + v[3][0].y*b1;
        r0.z = v[2][0].z*b0 + v[3][0].z*b1; r0.w = v[2][0].w*b0 + v[3][0].w*b1;
        r1.x = v[2][1].x*b0 + v[3][1].x*b1; r1.y = v[2][1].y*b0 + v[3][1].y*b1;
        r1.z = v[2][1].z*b0 + v[3][1].z*b1; r1.w = v[2][1].w*b0 + v[3][1].w*b1;
    } else {
        r0.x = v[0][0].x*a0 + v[1][0].x*a1; r0.y = v[0][0].y*a0 + v[1][0].y*a1;
        r0.z = v[0][0].z*a0 + v[1][0].z*a1; r0.w = v[0][0].w*a0 + v[1][0].w*a1;
        r1.x = v[0][1].x*a0 + v[1][1].x*a1; r1.y = v[0][1].y*a0 + v[1][1].y*a1;
        r1.z = v[0][1].z*a0 + v[1][1].z*a1; r1.w = v[0][1].w*a0 + v[1][1].w*a1;
    }
    float4* o4 = (float4*)(out + (size_t)n * 256);
    o4[lane]      = r0;
    o4[lane + 32] = r1;
}

// ---------------- launch ---------------------------------------------------------
extern "C" void kernel_launch(void* const* d_in, const int* in_sizes, int n_in,
                              void* d_out, int out_size) {
    const float* feature = (const float*)d_in[0];
    const int*   src     = (const int*)  d_in[1];
    const int*   dst     = (const int*)  d_in[2];
    const void*  tmask   =               d_in[3];
    const float* Wl      = (const float*)d_in[4];
    const float* a_src   = (const float*)d_in[5];
    const float* a_dst   = (const float*)d_in[6];
    const float* bias    = (const float*)d_in[7];
    const float* Dw      = (const float*)d_in[8];
    const float* Db      = (const float*)d_in[9];
    const float* Ww      = (const float*)d_in[10];
    const float* Wb      = (const float*)d_in[11];
    float* out = (float*)d_out;

    detect_kernel<<<1, 256>>>((const unsigned char*)tmask);
    init_kernel<<<50000, 256>>>();
    gemm_kernel<<<dim3(16, 391), 256>>>(feature, Wl);
    attn_coef_kernel<<<100000, 256>>>(a_src, a_dst);
    edge_max_kernel<<<12500, 256>>>(src, dst);
    edge_expsum_kernel<<<12500, 256>>>(src, dst);
    scatter_kernel<<<800000, 256>>>(src, dst);
    finalize_kernel<<<50000, 256>>>(bias);
    aggregate_kernel<<<6250, 256>>>(tmask, Dw, Db, Ww, Wb, out);
}

// round 2
// speedup vs baseline: 2.2681x; 2.2681x over previous
#include <cuda_runtime.h>
#include <math.h>

#define N_NODES 50000
#define N_EDGES 800000
#define NC 4
#define NH 4
#define OUT_F 64
#define J_DIM 1024            // NC*NH*OUT_F
#define SEG_TOT (NC * N_NODES)   // 200000 (channel,dst) segments
#define SCAN_BLOCKS 196          // ceil(200000/1024)

// ---------------- scratch (device globals; no allocations allowed) ----------
__device__ __align__(16) float    g_Wh [(size_t)N_NODES * J_DIM];
__device__ __align__(16) float    g_acc[(size_t)N_NODES * J_DIM];   // final H per channel
__device__ __align__(16) float    g_el [N_NODES * 16];
__device__ __align__(16) float    g_er [N_NODES * 16];
__device__ __align__(16) unsigned g_menc[N_NODES * 16];
__device__ __align__(16) float    g_den [N_NODES * 16];
__device__ __align__(16) float    g_ex  [(size_t)NC * N_EDGES * 4];
// CSR machinery
__device__ int   g_cnt[SEG_TOT];
__device__ int   g_off[SEG_TOT];
__device__ int   g_cur[SEG_TOT];
__device__ int   g_bsum[SCAN_BLOCKS + 64];
__device__ int   g_csr_src[(size_t)NC * N_EDGES];
__device__ __align__(16) float g_csr_w[(size_t)NC * N_EDGES * 4];
__device__ int g_mask_mode;

// ---------------- helpers ----------------------------------------------------
__device__ __forceinline__ float warpsum(float v) {
    #pragma unroll
    for (int o = 16; o; o >>= 1) v += __shfl_xor_sync(0xffffffffu, v, o);
    return v;
}
__device__ __forceinline__ unsigned fenc(float f) {
    unsigned u = __float_as_uint(f);
    return (u >> 31) ? ~u : (u | 0x80000000u);
}
__device__ __forceinline__ float fdec(unsigned u) {
    return (u & 0x80000000u) ? __uint_as_float(u ^ 0x80000000u) : __uint_as_float(~u);
}
__device__ __forceinline__ float leaky(float x) { return x > 0.f ? x : 0.2f * x; }

// ---------------- 0. sniff type_mask dtype -----------------------------------
__global__ void detect_kernel(const unsigned char* __restrict__ tm) {
    __shared__ int sawNZ123, sawF32;
    if (threadIdx.x == 0) { sawNZ123 = 0; sawF32 = 0; }
    __syncthreads();
    int nz = 0, f32 = 0;
    for (int i = threadIdx.x; i < 12500; i += blockDim.x) {
        unsigned char b1 = tm[4*i+1], b2 = tm[4*i+2], b3 = tm[4*i+3];
        if (b1 | b2 | b3) nz = 1;
        if (b2 == 0x80 && b3 == 0x3f) f32 = 1;
    }
    if (nz)  atomicOr(&sawNZ123, 1);
    if (f32) atomicOr(&sawF32, 1);
    __syncthreads();
    if (threadIdx.x == 0) g_mask_mode = sawF32 ? 2 : (sawNZ123 ? 0 : 1);
}

// ---------------- 1. init scratch ---------------------------------------------
__global__ void init_kernel() {
    int i = blockIdx.x * 256 + threadIdx.x;           // 800000 threads
    if (i < N_NODES * 16) {
        g_menc[i] = 0x007FFFFFu;   // fenc(-inf)
        g_den[i]  = 0.f;
    }
    if (i < SEG_TOT) g_cnt[i] = 0;
}

// ---------------- 2. projection GEMM ------------------------------------------
__global__ void gemm_kernel(const float* __restrict__ A, const float* __restrict__ W) {
    __shared__ float As[16][132];
    __shared__ float Bs[16][68];
    const int bm = blockIdx.y * 128;
    const int bn = blockIdx.x * 64;
    const int tid = threadIdx.x;
    const int tm = (tid >> 4) << 3;
    const int tn = (tid & 15) << 2;
    float acc[8][4];
    #pragma unroll
    for (int i = 0; i < 8; i++)
        #pragma unroll
        for (int j = 0; j < 4; j++) acc[i][j] = 0.f;

    for (int k0 = 0; k0 < 256; k0 += 16) {
        #pragma unroll
        for (int it = 0; it < 2; ++it) {
            int l = tid + it * 256;
            int row = l >> 2, seg = l & 3;
            int grow = bm + row; if (grow >= N_NODES) grow = N_NODES - 1;
            float4 v = *(const float4*)&A[(size_t)grow * 256 + k0 + seg * 4];
            As[seg*4+0][row] = v.x; As[seg*4+1][row] = v.y;
            As[seg*4+2][row] = v.z; As[seg*4+3][row] = v.w;
        }
        {
            int j = tid >> 2, seg = tid & 3;
            float4 v = *(const float4*)&W[(size_t)(bn + j) * 256 + k0 + seg * 4];
            Bs[seg*4+0][j] = v.x; Bs[seg*4+1][j] = v.y;
            Bs[seg*4+2][j] = v.z; Bs[seg*4+3][j] = v.w;
        }
        __syncthreads();
        #pragma unroll
        for (int k = 0; k < 16; k++) {
            float4 a0 = *(const float4*)&As[k][tm];
            float4 a1 = *(const float4*)&As[k][tm + 4];
            float4 b  = *(const float4*)&Bs[k][tn];
            float av[8] = {a0.x,a0.y,a0.z,a0.w,a1.x,a1.y,a1.z,a1.w};
            float bv[4] = {b.x,b.y,b.z,b.w};
            #pragma unroll
            for (int i = 0; i < 8; i++)
                #pragma unroll
                for (int j = 0; j < 4; j++)
                    acc[i][j] += av[i] * bv[j];
        }
        __syncthreads();
    }
    #pragma unroll
    for (int i = 0; i < 8; i++) {
        int grow = bm + tm + i;
        if (grow < N_NODES) {
            float4 v = make_float4(acc[i][0], acc[i][1], acc[i][2], acc[i][3]);
            *(float4*)&g_Wh[(size_t)grow * J_DIM + bn + tn] = v;
        }
    }
}

// ---------------- 3. attention coefficients el/er ------------------------------
__global__ void attn_coef_kernel(const float* __restrict__ a_src, const float* __restrict__ a_dst) {
    int wid  = (blockIdx.x * blockDim.x + threadIdx.x) >> 5;
    int lane = threadIdx.x & 31;
    if (wid >= N_NODES * 16) return;
    int n = wid >> 4, ch = wid & 15;
    const float* wrow = g_Wh + (size_t)n * J_DIM + ch * 64;
    float w0 = wrow[lane], w1 = wrow[lane + 32];
    float s1 = w0 * __ldg(&a_src[ch*64 + lane]) + w1 * __ldg(&a_src[ch*64 + lane + 32]);
    float s2 = w0 * __ldg(&a_dst[ch*64 + lane]) + w1 * __ldg(&a_dst[ch*64 + lane + 32]);
    s1 = warpsum(s1); s2 = warpsum(s2);
    if (lane == 0) { g_el[wid] = s1; g_er[wid] = s2; }
}

// ---------------- 4. segment max + degree histogram -----------------------------
__global__ void edge_max_kernel(const int* __restrict__ src, const int* __restrict__ dst) {
    int idx = blockIdx.x * blockDim.x + threadIdx.x;
    if (idx >= NC * N_EDGES) return;
    int c = idx / N_EDGES;
    int s = src[idx], d = dst[idx];
    float4 elv = *(const float4*)&g_el[s * 16 + c * 4];
    float4 erv = *(const float4*)&g_er[d * 16 + c * 4];
    float vx[4] = {elv.x+erv.x, elv.y+erv.y, elv.z+erv.z, elv.w+erv.w};
    #pragma unroll
    for (int h = 0; h < 4; h++)
        atomicMax(&g_menc[d * 16 + c * 4 + h], fenc(leaky(vx[h])));
    atomicAdd(&g_cnt[c * N_NODES + d], 1);
}

// ---------------- 5. exp + denominator sums ------------------------------------
__global__ void edge_expsum_kernel(const int* __restrict__ src, const int* __restrict__ dst) {
    int idx = blockIdx.x * blockDim.x + threadIdx.x;
    if (idx >= NC * N_EDGES) return;
    int c = idx / N_EDGES;
    int s = src[idx], d = dst[idx];
    float4 elv = *(const float4*)&g_el[s * 16 + c * 4];
    float4 erv = *(const float4*)&g_er[d * 16 + c * 4];
    float vx[4] = {elv.x+erv.x, elv.y+erv.y, elv.z+erv.z, elv.w+erv.w};
    float exv[4];
    #pragma unroll
    for (int h = 0; h < 4; h++) {
        float m = fdec(g_menc[d * 16 + c * 4 + h]);
        float ex = __expf(leaky(vx[h]) - m);
        exv[h] = ex;
        atomicAdd(&g_den[d * 16 + c * 4 + h], ex);
    }
    *(float4*)&g_ex[(size_t)idx * 4] = make_float4(exv[0], exv[1], exv[2], exv[3]);
}

// ---------------- 6a/6b/6c. exclusive scan of g_cnt -> g_off --------------------
__global__ void scan1_kernel() {
    __shared__ int sh[1024];
    int t = threadIdx.x, b = blockIdx.x;
    int i = b * 1024 + t;
    int v = (i < SEG_TOT) ? g_cnt[i] : 0;
    sh[t] = v;
    __syncthreads();
    #pragma unroll
    for (int off = 1; off < 1024; off <<= 1) {
        int x = (t >= off) ? sh[t - off] : 0;
        __syncthreads();
        sh[t] += x;
        __syncthreads();
    }
    if (i < SEG_TOT) g_off[i] = sh[t] - v;   // exclusive (local)
    if (t == 1023) g_bsum[b] = sh[t];
}
__global__ void scan2_kernel() {
    __shared__ int sh[256];
    int t = threadIdx.x;
    int v = (t < SCAN_BLOCKS) ? g_bsum[t] : 0;
    sh[t] = v;
    __syncthreads();
    #pragma unroll
    for (int off = 1; off < 256; off <<= 1) {
        int x = (t >= off) ? sh[t - off] : 0;
        __syncthreads();
        sh[t] += x;
        __syncthreads();
    }
    if (t < SCAN_BLOCKS) g_bsum[t] = sh[t] - v;  // exclusive block offsets
}
__global__ void scan3_kernel() {
    int t = threadIdx.x, b = blockIdx.x;
    int i = b * 1024 + t;
    if (i < SEG_TOT) {
        int o = g_off[i] + g_bsum[b];
        g_off[i] = o;
        g_cur[i] = o;
    }
}

// ---------------- 7. permute edges into CSR, fold softmax normalization ---------
__global__ void permute_kernel(const int* __restrict__ src, const int* __restrict__ dst) {
    int idx = blockIdx.x * blockDim.x + threadIdx.x;
    if (idx >= NC * N_EDGES) return;
    int c = idx / N_EDGES;
    int d = dst[idx], s = src[idx];
    int p = atomicAdd(&g_cur[c * N_NODES + d], 1);
    g_csr_src[p] = s;
    float4 ex = *(const float4*)&g_ex[(size_t)idx * 4];
    float4 dn = *(const float4*)&g_den[d * 16 + c * 4];
    float4 w = make_float4(ex.x / dn.x, ex.y / dn.y, ex.z / dn.z, ex.w / dn.w);
    *(float4*)&g_csr_w[(size_t)p * 4] = w;
}

// ---------------- 8. gather (no atomics) + fused residual+bias+elu --------------
__global__ void gather_kernel(const float* __restrict__ bias) {
    int wid  = (blockIdx.x * 256 + threadIdx.x) >> 5;  // (c,d) segment
    int lane = threadIdx.x & 31;
    if (wid >= SEG_TOT) return;
    int c = wid / N_NODES;
    int d = wid - c * N_NODES;
    int start = g_off[wid];
    int cnt   = g_cnt[wid];
    int h = lane >> 3;               // head for this lane's 8 floats
    const int coff = c * 256 + lane * 8;

    float a0=0.f,a1=0.f,a2=0.f,a3=0.f,a4=0.f,a5=0.f,a6=0.f,a7=0.f;
    for (int i = 0; i < cnt; i++) {
        int   s = g_csr_src[start + i];
        float w = g_csr_w[(size_t)(start + i) * 4 + h];
        const float4* p = (const float4*)&g_Wh[(size_t)s * J_DIM + coff];
        float4 v0 = p[0], v1 = p[1];
        a0 += w * v0.x; a1 += w * v0.y; a2 += w * v0.z; a3 += w * v0.w;
        a4 += w * v1.x; a5 += w * v1.y; a6 += w * v1.z; a7 += w * v1.w;
    }
    size_t base = (size_t)d * J_DIM + coff;
    const float4* wp = (const float4*)&g_Wh[base];
    float4 wv0 = wp[0], wv1 = wp[1];
    const float4* bp = (const float4*)&bias[coff];
    float4 b0 = bp[0], b1 = bp[1];
    float x;
    float4 r0, r1;
    x = a0 + wv0.x + b0.x; r0.x = x > 0.f ? x : expm1f(x);
    x = a1 + wv0.y + b0.y; r0.y = x > 0.f ? x : expm1f(x);
    x = a2 + wv0.z + b0.z; r0.z = x > 0.f ? x : expm1f(x);
    x = a3 + wv0.w + b0.w; r0.w = x > 0.f ? x : expm1f(x);
    x = a4 + wv1.x + b1.x; r1.x = x > 0.f ? x : expm1f(x);
    x = a5 + wv1.y + b1.y; r1.y = x > 0.f ? x : expm1f(x);
    x = a6 + wv1.z + b1.z; r1.z = x > 0.f ? x : expm1f(x);
    x = a7 + wv1.w + b1.w; r1.w = x > 0.f ? x : expm1f(x);
    *(float4*)&g_acc[base]     = r0;
    *(float4*)&g_acc[base + 4] = r1;
}

// ---------------- 9. channel aggregation + type select --------------------------
__global__ void aggregate_kernel(const void* __restrict__ tm,
                                 const float* __restrict__ Dw, const float* __restrict__ Db,
                                 const float* __restrict__ Ww, const float* __restrict__ Wb,
                                 float* __restrict__ out) {
    int wid  = (blockIdx.x * blockDim.x + threadIdx.x) >> 5;
    int lane = threadIdx.x & 31;
    if (wid >= N_NODES) return;
    int n = wid;
    const float4* H = (const float4*)(g_acc + (size_t)n * J_DIM);
    float4 v[4][2];
    #pragma unroll
    for (int ch = 0; ch < 4; ch++) {
        v[ch][0] = H[ch * 64 + lane];
        v[ch][1] = H[ch * 64 + lane + 32];
    }
    float dl[2], wl[2];
    #pragma unroll
    for (int r = 0; r < 2; r++) {
        const float4* DwR = (const float4*)(Dw + r * 512);
        const float4* WwR = (const float4*)(Ww + r * 512);
        float4 d0 = DwR[lane], d1 = DwR[lane+32], d2 = DwR[64+lane], d3 = DwR[64+lane+32];
        float4 w0 = WwR[lane], w1 = WwR[lane+32], w2 = WwR[64+lane], w3 = WwR[64+lane+32];
        float sD = v[0][0].x*d0.x + v[0][0].y*d0.y + v[0][0].z*d0.z + v[0][0].w*d0.w
                 + v[0][1].x*d1.x + v[0][1].y*d1.y + v[0][1].z*d1.z + v[0][1].w*d1.w
                 + v[1][0].x*d2.x + v[1][0].y*d2.y + v[1][0].z*d2.z + v[1][0].w*d2.w
                 + v[1][1].x*d3.x + v[1][1].y*d3.y + v[1][1].z*d3.z + v[1][1].w*d3.w;
        float sW = v[2][0].x*w0.x + v[2][0].y*w0.y + v[2][0].z*w0.z + v[2][0].w*w0.w
                 + v[2][1].x*w1.x + v[2][1].y*w1.y + v[2][1].z*w1.z + v[2][1].w*w1.w
                 + v[3][0].x*w2.x + v[3][0].y*w2.y + v[3][0].z*w2.z + v[3][0].w*w2.w
                 + v[3][1].x*w3.x + v[3][1].y*w3.y + v[3][1].z*w3.z + v[3][1].w*w3.w;
        dl[r] = warpsum(sD) + __ldg(&Db[r]);
        wl[r] = warpsum(sW) + __ldg(&Wb[r]);
    }
    float mD = fmaxf(dl[0], dl[1]);
    float e0 = __expf(dl[0] - mD), e1 = __expf(dl[1] - mD);
    float a0 = e0 / (e0 + e1), a1 = e1 / (e0 + e1);
    float mW = fmaxf(wl[0], wl[1]);
    float f0 = __expf(wl[0] - mW), f1 = __expf(wl[1] - mW);
    float b0 = f0 / (f0 + f1), b1 = f1 / (f0 + f1);

    int mode = g_mask_mode;
    bool msk;
    if (mode == 1)      msk = ((const int*)tm)[n] != 0;
    else if (mode == 2) msk = ((const float*)tm)[n] != 0.f;
    else                msk = ((const unsigned char*)tm)[n] != 0;

    float4 r0, r1;
    if (msk) {
        r0.x = v[2][0].x*b0 + v[3][0].x*b1; r0.y = v[2][0].y*b0 + v[3][0].y*b1;
        r0.z = v[2][0].z*b0 + v[3][0].z*b1; r0.w = v[2][0].w*b0 + v[3][0].w*b1;
        r1.x = v[2][1].x*b0 + v[3][1].x*b1; r1.y = v[2][1].y*b0 + v[3][1].y*b1;
        r1.z = v[2][1].z*b0 + v[3][1].z*b1; r1.w = v[2][1].w*b0 + v[3][1].w*b1;
    } else {
        r0.x = v[0][0].x*a0 + v[1][0].x*a1; r0.y = v[0][0].y*a0 + v[1][0].y*a1;
        r0.z = v[0][0].z*a0 + v[1][0].z*a1; r0.w = v[0][0].w*a0 + v[1][0].w*a1;
        r1.x = v[0][1].x*a0 + v[1][1].x*a1; r1.y = v[0][1].y*a0 + v[1][1].y*a1;
        r1.z = v[0][1].z*a0 + v[1][1].z*a1; r1.w = v[0][1].w*a0 + v[1][1].w*a1;
    }
    float4* o4 = (float4*)(out + (size_t)n * 256);
    o4[lane]      = r0;
    o4[lane + 32] = r1;
}

// ---------------- launch ---------------------------------------------------------
extern "C" void kernel_launch(void* const* d_in, const int* in_sizes, int n_in,
                              void* d_out, int out_size) {
    const float* feature = (const float*)d_in[0];
    const int*   src     = (const int*)  d_in[1];
    const int*   dst     = (const int*)  d_in[2];
    const void*  tmask   =               d_in[3];
    const float* Wl      = (const float*)d_in[4];
    const float* a_src   = (const float*)d_in[5];
    const float* a_dst   = (const float*)d_in[6];
    const float* bias    = (const float*)d_in[7];
    const float* Dw      = (const float*)d_in[8];
    const float* Db      = (const float*)d_in[9];
    const float* Ww      = (const float*)d_in[10];
    const float* Wb      = (const float*)d_in[11];
    float* out = (float*)d_out;

    detect_kernel<<<1, 256>>>((const unsigned char*)tmask);
    init_kernel<<<3125, 256>>>();
    gemm_kernel<<<dim3(16, 391), 256>>>(feature, Wl);
    attn_coef_kernel<<<100000, 256>>>(a_src, a_dst);
    edge_max_kernel<<<12500, 256>>>(src, dst);
    edge_expsum_kernel<<<12500, 256>>>(src, dst);
    scan1_kernel<<<SCAN_BLOCKS, 1024>>>();
    scan2_kernel<<<1, 256>>>();
    scan3_kernel<<<SCAN_BLOCKS, 1024>>>();
    permute_kernel<<<12500, 256>>>(src, dst);
    gather_kernel<<<25000, 256>>>(bias);
    aggregate_kernel<<<6250, 256>>>(tmask, Dw, Db, Ww, Wb, out);
}

// round 4
// speedup vs baseline: 2.7557x; 1.2150x over previous
#include <cuda_runtime.h>
#include <cuda_bf16.h>
#include <math.h>
#include <stdint.h>

#define N_NODES 50000
#define N_EDGES 800000
#define NC 4
#define NH 4
#define OUT_F 64
#define J_DIM 1024
#define SEG_TOT (NC * N_NODES)
#define SCAN_BLOCKS 196

// ---------------- scratch (device globals; no allocations allowed) ----------
__device__ __align__(16) float    g_Wh [(size_t)N_NODES * J_DIM];
__device__ __align__(16) float    g_acc[(size_t)N_NODES * J_DIM];
__device__ __align__(16) float    g_el [N_NODES * 16];
__device__ __align__(16) float    g_er [N_NODES * 16];
__device__ __align__(16) unsigned g_menc[N_NODES * 16];
__device__ __align__(16) float    g_den [N_NODES * 16];
__device__ __align__(16) float    g_ex  [(size_t)NC * N_EDGES * 4];
__device__ int   g_cnt[SEG_TOT];
__device__ int   g_off[SEG_TOT];
__device__ int   g_cur[SEG_TOT];
__device__ int   g_bsum[SCAN_BLOCKS + 64];
__device__ int   g_csr_src[(size_t)NC * N_EDGES];
__device__ __align__(16) float g_csr_w[(size_t)NC * N_EDGES * 4];
__device__ int g_mask_mode;
// split-bf16 operands for tensor-core GEMM
__device__ __align__(16) __nv_bfloat16 g_Ahi[(size_t)N_NODES * 256];
__device__ __align__(16) __nv_bfloat16 g_Alo[(size_t)N_NODES * 256];
__device__ __align__(16) __nv_bfloat16 g_Bhi[1024 * 256];
__device__ __align__(16) __nv_bfloat16 g_Blo[1024 * 256];

// ---------------- generic helpers --------------------------------------------
__device__ __forceinline__ float warpsum(float v) {
    #pragma unroll
    for (int o = 16; o; o >>= 1) v += __shfl_xor_sync(0xffffffffu, v, o);
    return v;
}
__device__ __forceinline__ unsigned fenc(float f) {
    unsigned u = __float_as_uint(f);
    return (u >> 31) ? ~u : (u | 0x80000000u);
}
__device__ __forceinline__ float fdec(unsigned u) {
    return (u & 0x80000000u) ? __uint_as_float(u ^ 0x80000000u) : __uint_as_float(~u);
}
__device__ __forceinline__ float leaky(float x) { return x > 0.f ? x : 0.2f * x; }
__device__ __forceinline__ uint32_t smem_u32(const void* p) {
    uint32_t a;
    asm("{ .reg .u64 t; cvta.to.shared.u64 t, %1; cvt.u32.u64 %0, t; }" : "=r"(a) : "l"(p));
    return a;
}

// ---------------- 0. sniff type_mask dtype -----------------------------------
__global__ void detect_kernel(const unsigned char* __restrict__ tm) {
    __shared__ int sawNZ123, sawF32;
    if (threadIdx.x == 0) { sawNZ123 = 0; sawF32 = 0; }
    __syncthreads();
    int nz = 0, f32 = 0;
    for (int i = threadIdx.x; i < 12500; i += blockDim.x) {
        unsigned char b1 = tm[4*i+1], b2 = tm[4*i+2], b3 = tm[4*i+3];
        if (b1 | b2 | b3) nz = 1;
        if (b2 == 0x80 && b3 == 0x3f) f32 = 1;
    }
    if (nz)  atomicOr(&sawNZ123, 1);
    if (f32) atomicOr(&sawF32, 1);
    __syncthreads();
    if (threadIdx.x == 0) g_mask_mode = sawF32 ? 2 : (sawNZ123 ? 0 : 1);
}

// ---------------- 1. init + split operands into bf16 hi/lo ---------------------
__global__ void init_kernel() {
    int i = blockIdx.x * 256 + threadIdx.x;
    if (i < N_NODES * 16) {
        g_menc[i] = 0x007FFFFFu;
        g_den[i]  = 0.f;
    }
    if (i < SEG_TOT) g_cnt[i] = 0;
}
__global__ void split_kernel(const float* __restrict__ feat, const float* __restrict__ W) {
    int i = blockIdx.x * 256 + threadIdx.x;   // 12.8M
    if (i < N_NODES * 256) {
        float x = feat[i];
        __nv_bfloat16 h = __float2bfloat16(x);
        g_Ahi[i] = h;
        g_Alo[i] = __float2bfloat16(x - __bfloat162float(h));
    }
    if (i < 1024 * 256) {
        float x = W[i];
        __nv_bfloat16 h = __float2bfloat16(x);
        g_Bhi[i] = h;
        g_Blo[i] = __float2bfloat16(x - __bfloat162float(h));
    }
}

// ---------------- 2. mma.sync bf16 projection GEMM ------------------------------
// g_Wh[128mblk][128nblk] += A[128,256] @ B[256,256]^T, split-bf16 3 products
#define AOFF_HI 0
#define AOFF_LO 18432
#define BOFF_HI 36864
#define BOFF_LO 55296
#define SM_GEMM 73728
#define ROWB 144   // smem row stride in bytes (72 bf16)

__global__ void __launch_bounds__(256, 2) mma_gemm_kernel() {
    extern __shared__ char smem[];
    const uint32_t sbase = smem_u32(smem);
    const int tid = threadIdx.x;
    const int wid = tid >> 5, lane = tid & 31;
    const int bn = blockIdx.x * 128;
    const int bm = blockIdx.y * 128;
    const int m_base = (wid >> 2) * 64;
    const int n_base = (wid & 3) * 32;

    float acc[4][4][4];
    #pragma unroll
    for (int i = 0; i < 4; i++)
        #pragma unroll
        for (int j = 0; j < 4; j++)
            #pragma unroll
            for (int r = 0; r < 4; r++) acc[i][j][r] = 0.f;

    const int t4  = lane >> 3;     // tile index within ldmatrix
    const int lr  = lane & 7;
    // A-frag address components (x4): tiles (mlo/klo, mhi/klo, mlo/khi, mhi/khi)
    const int a_roff = m_base + lr + ((t4 & 1) << 3);
    const int a_coff = (t4 >> 1) << 3;
    // B-frag address components (x2): tiles (klo, khi); lanes>=16 replicate (ignored)
    const int b_roff = n_base + lr;
    const int b_coff = (t4 & 1) << 3;

    for (int kc = 0; kc < 4; kc++) {
        #pragma unroll
        for (int it = 0; it < 4; it++) {
            int i = tid + it * 256;          // 1024 uint4 per matrix
            int r = i >> 3, u = i & 7;
            int grow = bm + r; if (grow >= N_NODES) grow = N_NODES - 1;
            size_t ga = (size_t)grow * 256 + kc * 64 + u * 8;
            size_t gb = (size_t)(bn + r) * 256 + kc * 64 + u * 8;
            uint32_t so = r * ROWB + u * 16;
            *(uint4*)(smem + AOFF_HI + so) = *(const uint4*)(g_Ahi + ga);
            *(uint4*)(smem + AOFF_LO + so) = *(const uint4*)(g_Alo + ga);
            *(uint4*)(smem + BOFF_HI + so) = *(const uint4*)(g_Bhi + gb);
            *(uint4*)(smem + BOFF_LO + so) = *(const uint4*)(g_Blo + gb);
        }
        __syncthreads();
        #pragma unroll
        for (int p = 0; p < 3; p++) {
            const uint32_t Abase = sbase + ((p == 2) ? AOFF_LO : AOFF_HI);
            const uint32_t Bbase = sbase + ((p == 1) ? BOFF_LO : BOFF_HI);
            #pragma unroll
            for (int ks = 0; ks < 4; ks++) {
                uint32_t a[4][4], b[4][2];
                #pragma unroll
                for (int i = 0; i < 4; i++) {
                    uint32_t aaddr = Abase + (a_roff + i * 16) * ROWB + (ks * 16 + a_coff) * 2;
                    asm volatile("ldmatrix.sync.aligned.m8n8.x4.shared.b16 {%0,%1,%2,%3}, [%4];"
                        : "=r"(a[i][0]), "=r"(a[i][1]), "=r"(a[i][2]), "=r"(a[i][3]) : "r"(aaddr));
                }
                #pragma unroll
                for (int j = 0; j < 4; j++) {
                    uint32_t baddr = Bbase + (b_roff + j * 8) * ROWB + (ks * 16 + b_coff) * 2;
                    asm volatile("ldmatrix.sync.aligned.m8n8.x2.shared.b16 {%0,%1}, [%2];"
                        : "=r"(b[j][0]), "=r"(b[j][1]) : "r"(baddr));
                }
                #pragma unroll
                for (int i = 0; i < 4; i++)
                    #pragma unroll
                    for (int j = 0; j < 4; j++)
                        asm volatile(
                            "mma.sync.aligned.m16n8k16.row.col.f32.bf16.bf16.f32 "
                            "{%0,%1,%2,%3}, {%4,%5,%6,%7}, {%8,%9}, {%0,%1,%2,%3};"
                            : "+f"(acc[i][j][0]), "+f"(acc[i][j][1]),
                              "+f"(acc[i][j][2]), "+f"(acc[i][j][3])
                            : "r"(a[i][0]), "r"(a[i][1]), "r"(a[i][2]), "r"(a[i][3]),
                              "r"(b[j][0]), "r"(b[j][1]));
            }
        }
        __syncthreads();
    }
    // epilogue
    #pragma unroll
    for (int i = 0; i < 4; i++) {
        int r0 = bm + m_base + i * 16 + (lane >> 2);
        int r1 = r0 + 8;
        #pragma unroll
        for (int j = 0; j < 4; j++) {
            int c = bn + n_base + j * 8 + (lane & 3) * 2;
            if (r0 < N_NODES)
                *(float2*)&g_Wh[(size_t)r0 * J_DIM + c] = make_float2(acc[i][j][0], acc[i][j][1]);
            if (r1 < N_NODES)
                *(float2*)&g_Wh[(size_t)r1 * J_DIM + c] = make_float2(acc[i][j][2], acc[i][j][3]);
        }
    }
}

// ---------------- 3. attention coefficients el/er ------------------------------
__global__ void attn_coef_kernel(const float* __restrict__ a_src, const float* __restrict__ a_dst) {
    int wid  = (blockIdx.x * blockDim.x + threadIdx.x) >> 5;
    int lane = threadIdx.x & 31;
    if (wid >= N_NODES * 16) return;
    int n = wid >> 4, ch = wid & 15;
    const float* wrow = g_Wh + (size_t)n * J_DIM + ch * 64;
    float w0 = wrow[lane], w1 = wrow[lane + 32];
    float s1 = w0 * __ldg(&a_src[ch*64 + lane]) + w1 * __ldg(&a_src[ch*64 + lane + 32]);
    float s2 = w0 * __ldg(&a_dst[ch*64 + lane]) + w1 * __ldg(&a_dst[ch*64 + lane + 32]);
    s1 = warpsum(s1); s2 = warpsum(s2);
    if (lane == 0) { g_el[wid] = s1; g_er[wid] = s2; }
}

// ---------------- 4. segment max + degree histogram -----------------------------
__global__ void edge_max_kernel(const int* __restrict__ src, const int* __restrict__ dst) {
    int idx = blockIdx.x * blockDim.x + threadIdx.x;
    if (idx >= NC * N_EDGES) return;
    int c = idx / N_EDGES;
    int s = src[idx], d = dst[idx];
    float4 elv = *(const float4*)&g_el[s * 16 + c * 4];
    float4 erv = *(const float4*)&g_er[d * 16 + c * 4];
    float vx[4] = {elv.x+erv.x, elv.y+erv.y, elv.z+erv.z, elv.w+erv.w};
    #pragma unroll
    for (int h = 0; h < 4; h++)
        atomicMax(&g_menc[d * 16 + c * 4 + h], fenc(leaky(vx[h])));
    atomicAdd(&g_cnt[c * N_NODES + d], 1);
}

// ---------------- 5. exp + denominator sums ------------------------------------
__global__ void edge_expsum_kernel(const int* __restrict__ src, const int* __restrict__ dst) {
    int idx = blockIdx.x * blockDim.x + threadIdx.x;
    if (idx >= NC * N_EDGES) return;
    int c = idx / N_EDGES;
    int s = src[idx], d = dst[idx];
    float4 elv = *(const float4*)&g_el[s * 16 + c * 4];
    float4 erv = *(const float4*)&g_er[d * 16 + c * 4];
    float vx[4] = {elv.x+erv.x, elv.y+erv.y, elv.z+erv.z, elv.w+erv.w};
    float exv[4];
    #pragma unroll
    for (int h = 0; h < 4; h++) {
        float m = fdec(g_menc[d * 16 + c * 4 + h]);
        float ex = __expf(leaky(vx[h]) - m);
        exv[h] = ex;
        atomicAdd(&g_den[d * 16 + c * 4 + h], ex);
    }
    *(float4*)&g_ex[(size_t)idx * 4] = make_float4(exv[0], exv[1], exv[2], exv[3]);
}

// ---------------- 6. exclusive scan of g_cnt -> g_off ---------------------------
__global__ void scan1_kernel() {
    __shared__ int sh[1024];
    int t = threadIdx.x, b = blockIdx.x;
    int i = b * 1024 + t;
    int v = (i < SEG_TOT) ? g_cnt[i] : 0;
    sh[t] = v;
    __syncthreads();
    #pragma unroll
    for (int off = 1; off < 1024; off <<= 1) {
        int x = (t >= off) ? sh[t - off] : 0;
        __syncthreads();
        sh[t] += x;
        __syncthreads();
    }
    if (i < SEG_TOT) g_off[i] = sh[t] - v;
    if (t == 1023) g_bsum[b] = sh[t];
}
__global__ void scan2_kernel() {
    __shared__ int sh[256];
    int t = threadIdx.x;
    int v = (t < SCAN_BLOCKS) ? g_bsum[t] : 0;
    sh[t] = v;
    __syncthreads();
    #pragma unroll
    for (int off = 1; off < 256; off <<= 1) {
        int x = (t >= off) ? sh[t - off] : 0;
        __syncthreads();
        sh[t] += x;
        __syncthreads();
    }
    if (t < SCAN_BLOCKS) g_bsum[t] = sh[t] - v;
}
__global__ void scan3_kernel() {
    int t = threadIdx.x, b = blockIdx.x;
    int i = b * 1024 + t;
    if (i < SEG_TOT) {
        int o = g_off[i] + g_bsum[b];
        g_off[i] = o;
        g_cur[i] = o;
    }
}

// ---------------- 7. permute edges into CSR, fold softmax normalization ---------
__global__ void permute_kernel(const int* __restrict__ src, const int* __restrict__ dst) {
    int idx = blockIdx.x * blockDim.x + threadIdx.x;
    if (idx >= NC * N_EDGES) return;
    int c = idx / N_EDGES;
    int d = dst[idx], s = src[idx];
    int p = atomicAdd(&g_cur[c * N_NODES + d], 1);
    g_csr_src[p] = s;
    float4 ex = *(const float4*)&g_ex[(size_t)idx * 4];
    float4 dn = *(const float4*)&g_den[d * 16 + c * 4];
    float4 w = make_float4(ex.x / dn.x, ex.y / dn.y, ex.z / dn.z, ex.w / dn.w);
    *(float4*)&g_csr_w[(size_t)p * 4] = w;
}

// ---------------- 8. gather (no atomics) + fused residual+bias+elu --------------
__global__ void gather_kernel(const float* __restrict__ bias) {
    int wid  = (blockIdx.x * 256 + threadIdx.x) >> 5;
    int lane = threadIdx.x & 31;
    if (wid >= SEG_TOT) return;
    int c = wid / N_NODES;
    int d = wid - c * N_NODES;
    int start = g_off[wid];
    int cnt   = g_cnt[wid];
    int h = lane >> 3;
    const int coff = c * 256 + lane * 8;

    float a0=0.f,a1=0.f,a2=0.f,a3=0.f,a4=0.f,a5=0.f,a6=0.f,a7=0.f;
    for (int i = 0; i < cnt; i++) {
        int   s = g_csr_src[start + i];
        float w = g_csr_w[(size_t)(start + i) * 4 + h];
        const float4* p = (const float4*)&g_Wh[(size_t)s * J_DIM + coff];
        float4 v0 = p[0], v1 = p[1];
        a0 += w * v0.x; a1 += w * v0.y; a2 += w * v0.z; a3 += w * v0.w;
        a4 += w * v1.x; a5 += w * v1.y; a6 += w * v1.z; a7 += w * v1.w;
    }
    size_t base = (size_t)d * J_DIM + coff;
    const float4* wp = (const float4*)&g_Wh[base];
    float4 wv0 = wp[0], wv1 = wp[1];
    const float4* bp = (const float4*)&bias[coff];
    float4 b0 = bp[0], b1 = bp[1];
    float x;
    float4 r0, r1;
    x = a0 + wv0.x + b0.x; r0.x = x > 0.f ? x : expm1f(x);
    x = a1 + wv0.y + b0.y; r0.y = x > 0.f ? x : expm1f(x);
    x = a2 + wv0.z + b0.z; r0.z = x > 0.f ? x : expm1f(x);
    x = a3 + wv0.w + b0.w; r0.w = x > 0.f ? x : expm1f(x);
    x = a4 + wv1.x + b1.x; r1.x = x > 0.f ? x : expm1f(x);
    x = a5 + wv1.y + b1.y; r1.y = x > 0.f ? x : expm1f(x);
    x = a6 + wv1.z + b1.z; r1.z = x > 0.f ? x : expm1f(x);
    x = a7 + wv1.w + b1.w; r1.w = x > 0.f ? x : expm1f(x);
    *(float4*)&g_acc[base]     = r0;
    *(float4*)&g_acc[base + 4] = r1;
}

// ---------------- 9. channel aggregation + type select --------------------------
__global__ void aggregate_kernel(const void* __restrict__ tm,
                                 const float* __restrict__ Dw, const float* __restrict__ Db,
                                 const float* __restrict__ Ww, const float* __restrict__ Wb,
                                 float* __restrict__ out) {
    int wid  = (blockIdx.x * blockDim.x + threadIdx.x) >> 5;
    int lane = threadIdx.x & 31;
    if (wid >= N_NODES) return;
    int n = wid;
    const float4* H = (const float4*)(g_acc + (size_t)n * J_DIM);
    float4 v[4][2];
    #pragma unroll
    for (int ch = 0; ch < 4; ch++) {
        v[ch][0] = H[ch * 64 + lane];
        v[ch][1] = H[ch * 64 + lane + 32];
    }
    float dl[2], wl[2];
    #pragma unroll
    for (int r = 0; r < 2; r++) {
        const float4* DwR = (const float4*)(Dw + r * 512);
        const float4* WwR = (const float4*)(Ww + r * 512);
        float4 d0 = DwR[lane], d1 = DwR[lane+32], d2 = DwR[64+lane], d3 = DwR[64+lane+32];
        float4 w0 = WwR[lane], w1 = WwR[lane+32], w2 = WwR[64+lane], w3 = WwR[64+lane+32];
        float sD = v[0][0].x*d0.x + v[0][0].y*d0.y + v[0][0].z*d0.z + v[0][0].w*d0.w
                 + v[0][1].x*d1.x + v[0][1].y*d1.y + v[0][1].z*d1.z + v[0][1].w*d1.w
                 + v[1][0].x*d2.x + v[1][0].y*d2.y + v[1][0].z*d2.z + v[1][0].w*d2.w
                 + v[1][1].x*d3.x + v[1][1].y*d3.y + v[1][1].z*d3.z + v[1][1].w*d3.w;
        float sW = v[2][0].x*w0.x + v[2][0].y*w0.y + v[2][0].z*w0.z + v[2][0].w*w0.w
                 + v[2][1].x*w1.x + v[2][1].y*w1.y + v[2][1].z*w1.z + v[2][1].w*w1.w
                 + v[3][0].x*w2.x + v[3][0].y*w2.y + v[3][0].z*w2.z + v[3][0].w*w2.w
                 + v[3][1].x*w3.x + v[3][1].y*w3.y + v[3][1].z*w3.z + v[3][1].w*w3.w;
        dl[r] = warpsum(sD) + __ldg(&Db[r]);
        wl[r] = warpsum(sW) + __ldg(&Wb[r]);
    }
    float mD = fmaxf(dl[0], dl[1]);
    float e0 = __expf(dl[0] - mD), e1 = __expf(dl[1] - mD);
    float a0 = e0 / (e0 + e1), a1 = e1 / (e0 + e1);
    float mW = fmaxf(wl[0], wl[1]);
    float f0 = __expf(wl[0] - mW), f1 = __expf(wl[1] - mW);
    float b0 = f0 / (f0 + f1), b1 = f1 / (f0 + f1);

    int mode = g_mask_mode;
    bool msk;
    if (mode == 1)      msk = ((const int*)tm)[n] != 0;
    else if (mode == 2) msk = ((const float*)tm)[n] != 0.f;
    else                msk = ((const unsigned char*)tm)[n] != 0;

    float4 r0, r1;
    if (msk) {
        r0.x = v[2][0].x*b0 + v[3][0].x*b1; r0.y = v[2][0].y*b0 + v[3][0].y*b1;
        r0.z = v[2][0].z*b0 + v[3][0].z*b1; r0.w = v[2][0].w*b0 + v[3][0].w*b1;
        r1.x = v[2][1].x*b0 + v[3][1].x*b1; r1.y = v[2][1].y*b0 + v[3][1].y*b1;
        r1.z = v[2][1].z*b0 + v[3][1].z*b1; r1.w = v[2][1].w*b0 + v[3][1].w*b1;
    } else {
        r0.x = v[0][0].x*a0 + v[1][0].x*a1; r0.y = v[0][0].y*a0 + v[1][0].y*a1;
        r0.z = v[0][0].z*a0 + v[1][0].z*a1; r0.w = v[0][0].w*a0 + v[1][0].w*a1;
        r1.x = v[0][1].x*a0 + v[1][1].x*a1; r1.y = v[0][1].y*a0 + v[1][1].y*a1;
        r1.z = v[0][1].z*a0 + v[1][1].z*a1; r1.w = v[0][1].w*a0 + v[1][1].w*a1;
    }
    float4* o4 = (float4*)(out + (size_t)n * 256);
    o4[lane]      = r0;
    o4[lane + 32] = r1;
}

// ---------------- launch ---------------------------------------------------------
extern "C" void kernel_launch(void* const* d_in, const int* in_sizes, int n_in,
                              void* d_out, int out_size) {
    const float* feature = (const float*)d_in[0];
    const int*   src     = (const int*)  d_in[1];
    const int*   dst     = (const int*)  d_in[2];
    const void*  tmask   =               d_in[3];
    const float* Wl      = (const float*)d_in[4];
    const float* a_src   = (const float*)d_in[5];
    const float* a_dst   = (const float*)d_in[6];
    const float* bias    = (const float*)d_in[7];
    const float* Dw      = (const float*)d_in[8];
    const float* Db      = (const float*)d_in[9];
    const float* Ww      = (const float*)d_in[10];
    const float* Wb      = (const float*)d_in[11];
    float* out = (float*)d_out;

    cudaFuncSetAttribute(mma_gemm_kernel, cudaFuncAttributeMaxDynamicSharedMemorySize, SM_GEMM);

    detect_kernel<<<1, 256>>>((const unsigned char*)tmask);
    init_kernel<<<3125, 256>>>();
    split_kernel<<<50000, 256>>>(feature, Wl);
    mma_gemm_kernel<<<dim3(8, 391), 256, SM_GEMM>>>();
    attn_coef_kernel<<<100000, 256>>>(a_src, a_dst);
    edge_max_kernel<<<12500, 256>>>(src, dst);
    edge_expsum_kernel<<<12500, 256>>>(src, dst);
    scan1_kernel<<<SCAN_BLOCKS, 1024>>>();
    scan2_kernel<<<1, 256>>>();
    scan3_kernel<<<SCAN_BLOCKS, 1024>>>();
    permute_kernel<<<12500, 256>>>(src, dst);
    gather_kernel<<<25000, 256>>>(bias);
    aggregate_kernel<<<6250, 256>>>(tmask, Dw, Db, Ww, Wb, out);
}

// round 5
// speedup vs baseline: 3.3003x; 1.1976x over previous
#include <cuda_runtime.h>
#include <cuda_bf16.h>
#include <math.h>
#include <stdint.h>

#define N_NODES 50000
#define N_EDGES 800000
#define NC 4
#define NH 4
#define OUT_F 64
#define J_DIM 1024
#define SEG_TOT (NC * N_NODES)
#define SCAN_BLOCKS 196

// ---------------- scratch (device globals; no allocations allowed) ----------
__device__ __align__(16) float    g_Wh [(size_t)N_NODES * J_DIM];
__device__ __align__(16) float    g_acc[(size_t)N_NODES * J_DIM];
__device__ __align__(16) float    g_el [N_NODES * 16];
__device__ __align__(16) float    g_er [N_NODES * 16];
__device__ __align__(16) unsigned g_menc[N_NODES * 16];
__device__ __align__(16) float    g_den [N_NODES * 16];
__device__ int   g_cnt[SEG_TOT];
__device__ int   g_off[SEG_TOT];
__device__ int   g_cur[SEG_TOT];
__device__ int   g_bsum[SCAN_BLOCKS + 64];
__device__ int   g_csr_src[(size_t)NC * N_EDGES];
__device__ __align__(16) float g_csr_w[(size_t)NC * N_EDGES * 4];
__device__ int g_mask_mode;
// split-bf16 operands for tensor-core GEMM
__device__ __align__(16) __nv_bfloat16 g_Ahi[(size_t)N_NODES * 256];
__device__ __align__(16) __nv_bfloat16 g_Alo[(size_t)N_NODES * 256];
__device__ __align__(16) __nv_bfloat16 g_Bhi[1024 * 256];
__device__ __align__(16) __nv_bfloat16 g_Blo[1024 * 256];

// ---------------- generic helpers --------------------------------------------
__device__ __forceinline__ float warpsum(float v) {
    #pragma unroll
    for (int o = 16; o; o >>= 1) v += __shfl_xor_sync(0xffffffffu, v, o);
    return v;
}
__device__ __forceinline__ unsigned fenc(float f) {
    unsigned u = __float_as_uint(f);
    return (u >> 31) ? ~u : (u | 0x80000000u);
}
__device__ __forceinline__ float fdec(unsigned u) {
    return (u & 0x80000000u) ? __uint_as_float(u ^ 0x80000000u) : __uint_as_float(~u);
}
__device__ __forceinline__ float leaky(float x) { return x > 0.f ? x : 0.2f * x; }
__device__ __forceinline__ uint32_t smem_u32(const void* p) {
    uint32_t a;
    asm("{ .reg .u64 t; cvta.to.shared.u64 t, %1; cvt.u32.u64 %0, t; }" : "=r"(a) : "l"(p));
    return a;
}
__device__ __forceinline__ void cpa16(uint32_t s, const void* g) {
    asm volatile("cp.async.cg.shared.global [%0], [%1], 16;" :: "r"(s), "l"(g));
}

// ---------------- 0. sniff type_mask dtype -----------------------------------
__global__ void detect_kernel(const unsigned char* __restrict__ tm) {
    __shared__ int sawNZ123, sawF32;
    if (threadIdx.x == 0) { sawNZ123 = 0; sawF32 = 0; }
    __syncthreads();
    int nz = 0, f32 = 0;
    for (int i = threadIdx.x; i < 12500; i += blockDim.x) {
        unsigned char b1 = tm[4*i+1], b2 = tm[4*i+2], b3 = tm[4*i+3];
        if (b1 | b2 | b3) nz = 1;
        if (b2 == 0x80 && b3 == 0x3f) f32 = 1;
    }
    if (nz)  atomicOr(&sawNZ123, 1);
    if (f32) atomicOr(&sawF32, 1);
    __syncthreads();
    if (threadIdx.x == 0) g_mask_mode = sawF32 ? 2 : (sawNZ123 ? 0 : 1);
}

// ---------------- 1. init + split operands into bf16 hi/lo ---------------------
__global__ void init_kernel() {
    int i = blockIdx.x * 256 + threadIdx.x;
    if (i < N_NODES * 16) {
        g_menc[i] = 0x007FFFFFu;
        g_den[i]  = 0.f;
    }
    if (i < SEG_TOT) g_cnt[i] = 0;
}
__global__ void split_kernel(const float* __restrict__ feat, const float* __restrict__ W) {
    int i = blockIdx.x * 256 + threadIdx.x;
    if (i < N_NODES * 256) {
        float x = feat[i];
        __nv_bfloat16 h = __float2bfloat16(x);
        g_Ahi[i] = h;
        g_Alo[i] = __float2bfloat16(x - __bfloat162float(h));
    }
    if (i < 1024 * 256) {
        float x = W[i];
        __nv_bfloat16 h = __float2bfloat16(x);
        g_Bhi[i] = h;
        g_Blo[i] = __float2bfloat16(x - __bfloat162float(h));
    }
}

// ---------------- 2. pipelined mma.sync GEMM + fused el/er ---------------------
// CTA tile 128(M) x 256(N); 8 warps in 2m x 4n; warp tile 64x64.
// K chunks of 64, double-buffered cp.async.
#define ROWB 144
#define ST_A_HI 0
#define ST_A_LO 18432
#define ST_B_HI 36864
#define ST_B_LO 73728
#define STAGE   110592
#define SM_GEMM (2 * STAGE)

#define LDMX4(r, addr) \
    asm volatile("ldmatrix.sync.aligned.m8n8.x4.shared.b16 {%0,%1,%2,%3}, [%4];" \
        : "=r"((r)[0]), "=r"((r)[1]), "=r"((r)[2]), "=r"((r)[3]) : "r"(addr))
#define MMA16816(d, a, b0, b1) \
    asm volatile("mma.sync.aligned.m16n8k16.row.col.f32.bf16.bf16.f32 " \
        "{%0,%1,%2,%3}, {%4,%5,%6,%7}, {%8,%9}, {%0,%1,%2,%3};" \
        : "+f"((d)[0]), "+f"((d)[1]), "+f"((d)[2]), "+f"((d)[3]) \
        : "r"((a)[0]), "r"((a)[1]), "r"((a)[2]), "r"((a)[3]), "r"(b0), "r"(b1))

__global__ void __launch_bounds__(256, 1)
mma_gemm_kernel(const float* __restrict__ asrc, const float* __restrict__ adst) {
    extern __shared__ char smem[];
    const uint32_t sbase = smem_u32(smem);
    const int tid = threadIdx.x;
    const int wid = tid >> 5, lane = tid & 31;
    const int bn = blockIdx.x * 256;
    const int bm = blockIdx.y * 128;
    const int m_base = (wid >> 2) * 64;
    const int n_base = (wid & 3) * 64;
    const int t4 = lane >> 3, lr = lane & 7;

    // stage loader: A 128x64 (hi/lo) + B 256x64 (hi/lo), 144B smem row stride
    auto load_stage = [&](int kc, int stg) {
        const uint32_t sp = sbase + stg * STAGE;
        #pragma unroll
        for (int it = 0; it < 4; it++) {
            int i = tid + it * 256;
            int r = i >> 3, u = i & 7;
            int grow = bm + r; if (grow >= N_NODES) grow = N_NODES - 1;
            size_t ga = (size_t)grow * 256 + kc * 64 + u * 8;
            uint32_t sa = sp + ST_A_HI + r * ROWB + u * 16;
            cpa16(sa, g_Ahi + ga);
            cpa16(sa + (ST_A_LO - ST_A_HI), g_Alo + ga);
        }
        #pragma unroll
        for (int it = 0; it < 8; it++) {
            int i = tid + it * 256;
            int r = i >> 3, u = i & 7;
            size_t gb = (size_t)(bn + r) * 256 + kc * 64 + u * 8;
            uint32_t sa = sp + ST_B_HI + r * ROWB + u * 16;
            cpa16(sa, g_Bhi + gb);
            cpa16(sa + (ST_B_LO - ST_B_HI), g_Blo + gb);
        }
        asm volatile("cp.async.commit_group;" ::: "memory");
    };

    float acc[4][8][4];
    #pragma unroll
    for (int i = 0; i < 4; i++)
        #pragma unroll
        for (int j = 0; j < 8; j++)
            #pragma unroll
            for (int r = 0; r < 4; r++) acc[i][j][r] = 0.f;

    load_stage(0, 0);

    const int a_roff = m_base + lr + ((t4 & 1) << 3);
    const int a_coff = (t4 >> 1) << 3;
    const int b_roff = n_base + lr + ((t4 >> 1) << 3);
    const int b_coff = (t4 & 1) << 3;

    for (int kc = 0; kc < 4; kc++) {
        asm volatile("cp.async.wait_group 0;" ::: "memory");
        __syncthreads();
        if (kc + 1 < 4) load_stage(kc + 1, (kc + 1) & 1);

        const uint32_t sp = sbase + (kc & 1) * STAGE;
        const uint32_t sAhi = sp + ST_A_HI, sAlo = sp + ST_A_LO;
        const uint32_t sBhi = sp + ST_B_HI, sBlo = sp + ST_B_LO;

        #pragma unroll
        for (int ks = 0; ks < 4; ks++) {
            const int kcol = ks * 16;
            uint32_t ahi[4][4], alo[4][4], bhi[4][4], blo[4][4];
            // load a_hi, b_hi
            #pragma unroll
            for (int i = 0; i < 4; i++) {
                uint32_t aa = sAhi + (a_roff + i * 16) * ROWB + (kcol + a_coff) * 2;
                LDMX4(ahi[i], aa);
            }
            #pragma unroll
            for (int q = 0; q < 4; q++) {
                uint32_t ba = sBhi + (b_roff + q * 16) * ROWB + (kcol + b_coff) * 2;
                LDMX4(bhi[q], ba);
            }
            // product 1: ah * bh
            #pragma unroll
            for (int i = 0; i < 4; i++)
                #pragma unroll
                for (int q = 0; q < 4; q++) {
                    MMA16816(acc[i][2*q],     ahi[i], bhi[q][0], bhi[q][1]);
                    MMA16816(acc[i][2*q + 1], ahi[i], bhi[q][2], bhi[q][3]);
                }
            // product 2: ah * bl
            #pragma unroll
            for (int q = 0; q < 4; q++) {
                uint32_t ba = sBlo + (b_roff + q * 16) * ROWB + (kcol + b_coff) * 2;
                LDMX4(blo[q], ba);
            }
            #pragma unroll
            for (int i = 0; i < 4; i++)
                #pragma unroll
                for (int q = 0; q < 4; q++) {
                    MMA16816(acc[i][2*q],     ahi[i], blo[q][0], blo[q][1]);
                    MMA16816(acc[i][2*q + 1], ahi[i], blo[q][2], blo[q][3]);
                }
            // product 3: al * bh
            #pragma unroll
            for (int i = 0; i < 4; i++) {
                uint32_t aa = sAlo + (a_roff + i * 16) * ROWB + (kcol + a_coff) * 2;
                LDMX4(alo[i], aa);
            }
            #pragma unroll
            for (int i = 0; i < 4; i++)
                #pragma unroll
                for (int q = 0; q < 4; q++) {
                    MMA16816(acc[i][2*q],     alo[i], bhi[q][0], bhi[q][1]);
                    MMA16816(acc[i][2*q + 1], alo[i], bhi[q][2], bhi[q][3]);
                }
        }
        __syncthreads();
    }

    // ---------- epilogue: store Wh + fused el/er ----------
    // attention vectors for this warp's 64-col head slice
    float ascv[8][2], adcv[8][2];
    #pragma unroll
    for (int j = 0; j < 8; j++) {
        int col = bn + n_base + j * 8 + (lane & 3) * 2;
        ascv[j][0] = __ldg(&asrc[col]);     ascv[j][1] = __ldg(&asrc[col + 1]);
        adcv[j][0] = __ldg(&adst[col]);     adcv[j][1] = __ldg(&adst[col + 1]);
    }
    const int cidx = blockIdx.x * 4 + (wid & 3);   // (channel, head)

    #pragma unroll
    for (int i = 0; i < 4; i++) {
        int r0 = bm + m_base + i * 16 + (lane >> 2);
        int r1 = r0 + 8;
        float e0 = 0.f, e1 = 0.f, f0 = 0.f, f1 = 0.f;
        #pragma unroll
        for (int j = 0; j < 8; j++) {
            int c = bn + n_base + j * 8 + (lane & 3) * 2;
            if (r0 < N_NODES)
                *(float2*)&g_Wh[(size_t)r0 * J_DIM + c] = make_float2(acc[i][j][0], acc[i][j][1]);
            if (r1 < N_NODES)
                *(float2*)&g_Wh[(size_t)r1 * J_DIM + c] = make_float2(acc[i][j][2], acc[i][j][3]);
            e0 += acc[i][j][0] * ascv[j][0] + acc[i][j][1] * ascv[j][1];
            f0 += acc[i][j][0] * adcv[j][0] + acc[i][j][1] * adcv[j][1];
            e1 += acc[i][j][2] * ascv[j][0] + acc[i][j][3] * ascv[j][1];
            f1 += acc[i][j][2] * adcv[j][0] + acc[i][j][3] * adcv[j][1];
        }
        #pragma unroll
        for (int o = 1; o < 4; o <<= 1) {
            e0 += __shfl_xor_sync(0xffffffffu, e0, o);
            e1 += __shfl_xor_sync(0xffffffffu, e1, o);
            f0 += __shfl_xor_sync(0xffffffffu, f0, o);
            f1 += __shfl_xor_sync(0xffffffffu, f1, o);
        }
        if ((lane & 3) == 0) {
            if (r0 < N_NODES) { g_el[r0 * 16 + cidx] = e0; g_er[r0 * 16 + cidx] = f0; }
            if (r1 < N_NODES) { g_el[r1 * 16 + cidx] = e1; g_er[r1 * 16 + cidx] = f1; }
        }
    }
}

// ---------------- 4. segment max + degree histogram -----------------------------
__global__ void edge_max_kernel(const int* __restrict__ src, const int* __restrict__ dst) {
    int idx = blockIdx.x * blockDim.x + threadIdx.x;
    if (idx >= NC * N_EDGES) return;
    int c = idx / N_EDGES;
    int s = src[idx], d = dst[idx];
    float4 elv = *(const float4*)&g_el[s * 16 + c * 4];
    float4 erv = *(const float4*)&g_er[d * 16 + c * 4];
    float vx[4] = {elv.x+erv.x, elv.y+erv.y, elv.z+erv.z, elv.w+erv.w};
    #pragma unroll
    for (int h = 0; h < 4; h++)
        atomicMax(&g_menc[d * 16 + c * 4 + h], fenc(leaky(vx[h])));
    atomicAdd(&g_cnt[c * N_NODES + d], 1);
}

// ---------------- 5. exclusive scan of g_cnt -> g_off ---------------------------
__global__ void scan1_kernel() {
    __shared__ int sh[1024];
    int t = threadIdx.x, b = blockIdx.x;
    int i = b * 1024 + t;
    int v = (i < SEG_TOT) ? g_cnt[i] : 0;
    sh[t] = v;
    __syncthreads();
    #pragma unroll
    for (int off = 1; off < 1024; off <<= 1) {
        int x = (t >= off) ? sh[t - off] : 0;
        __syncthreads();
        sh[t] += x;
        __syncthreads();
    }
    if (i < SEG_TOT) g_off[i] = sh[t] - v;
    if (t == 1023) g_bsum[b] = sh[t];
}
__global__ void scan2_kernel() {
    __shared__ int sh[256];
    int t = threadIdx.x;
    int v = (t < SCAN_BLOCKS) ? g_bsum[t] : 0;
    sh[t] = v;
    __syncthreads();
    #pragma unroll
    for (int off = 1; off < 256; off <<= 1) {
        int x = (t >= off) ? sh[t - off] : 0;
        __syncthreads();
        sh[t] += x;
        __syncthreads();
    }
    if (t < SCAN_BLOCKS) g_bsum[t] = sh[t] - v;
}
__global__ void scan3_kernel() {
    int t = threadIdx.x, b = blockIdx.x;
    int i = b * 1024 + t;
    if (i < SEG_TOT) {
        int o = g_off[i] + g_bsum[b];
        g_off[i] = o;
        g_cur[i] = o;
    }
}

// ---------------- 6. fused exp + denominator + CSR permute ----------------------
__global__ void expsum_permute_kernel(const int* __restrict__ src, const int* __restrict__ dst) {
    int idx = blockIdx.x * blockDim.x + threadIdx.x;
    if (idx >= NC * N_EDGES) return;
    int c = idx / N_EDGES;
    int s = src[idx], d = dst[idx];
    float4 elv = *(const float4*)&g_el[s * 16 + c * 4];
    float4 erv = *(const float4*)&g_er[d * 16 + c * 4];
    float vx[4] = {elv.x+erv.x, elv.y+erv.y, elv.z+erv.z, elv.w+erv.w};
    float exv[4];
    #pragma unroll
    for (int h = 0; h < 4; h++) {
        float m = fdec(g_menc[d * 16 + c * 4 + h]);
        float ex = __expf(leaky(vx[h]) - m);
        exv[h] = ex;
        atomicAdd(&g_den[d * 16 + c * 4 + h], ex);
    }
    int p = atomicAdd(&g_cur[c * N_NODES + d], 1);
    g_csr_src[p] = s;
    *(float4*)&g_csr_w[(size_t)p * 4] = make_float4(exv[0], exv[1], exv[2], exv[3]);
}

// ---------------- 7. gather (no atomics) + fused residual+bias+elu --------------
__global__ void gather_kernel(const float* __restrict__ bias) {
    int wid  = (blockIdx.x * 256 + threadIdx.x) >> 5;
    int lane = threadIdx.x & 31;
    if (wid >= SEG_TOT) return;
    int c = wid / N_NODES;
    int d = wid - c * N_NODES;
    int start = g_off[wid];
    int cnt   = g_cnt[wid];
    int h = lane >> 3;
    const int coff = c * 256 + lane * 8;
    float rd = 1.0f / g_den[d * 16 + c * 4 + h];   // cnt==0 -> unused inf

    float a0=0.f,a1=0.f,a2=0.f,a3=0.f,a4=0.f,a5=0.f,a6=0.f,a7=0.f;
    int   sN = 0; float wN = 0.f;
    if (cnt > 0) { sN = g_csr_src[start]; wN = g_csr_w[(size_t)start * 4 + h]; }
    for (int i = 0; i < cnt; i++) {
        int sC = sN; float wC = wN;
        if (i + 1 < cnt) {
            sN = g_csr_src[start + i + 1];
            wN = g_csr_w[(size_t)(start + i + 1) * 4 + h];
        }
        float w = wC * rd;
        const float4* p = (const float4*)&g_Wh[(size_t)sC * J_DIM + coff];
        float4 v0 = p[0], v1 = p[1];
        a0 += w * v0.x; a1 += w * v0.y; a2 += w * v0.z; a3 += w * v0.w;
        a4 += w * v1.x; a5 += w * v1.y; a6 += w * v1.z; a7 += w * v1.w;
    }
    size_t base = (size_t)d * J_DIM + coff;
    const float4* wp = (const float4*)&g_Wh[base];
    float4 wv0 = wp[0], wv1 = wp[1];
    const float4* bp = (const float4*)&bias[coff];
    float4 b0 = bp[0], b1 = bp[1];
    float x;
    float4 r0, r1;
    x = a0 + wv0.x + b0.x; r0.x = x > 0.f ? x : expm1f(x);
    x = a1 + wv0.y + b0.y; r0.y = x > 0.f ? x : expm1f(x);
    x = a2 + wv0.z + b0.z; r0.z = x > 0.f ? x : expm1f(x);
    x = a3 + wv0.w + b0.w; r0.w = x > 0.f ? x : expm1f(x);
    x = a4 + wv1.x + b1.x; r1.x = x > 0.f ? x : expm1f(x);
    x = a5 + wv1.y + b1.y; r1.y = x > 0.f ? x : expm1f(x);
    x = a6 + wv1.z + b1.z; r1.z = x > 0.f ? x : expm1f(x);
    x = a7 + wv1.w + b1.w; r1.w = x > 0.f ? x : expm1f(x);
    *(float4*)&g_acc[base]     = r0;
    *(float4*)&g_acc[base + 4] = r1;
}

// ---------------- 8. channel aggregation + type select --------------------------
__global__ void aggregate_kernel(const void* __restrict__ tm,
                                 const float* __restrict__ Dw, const float* __restrict__ Db,
                                 const float* __restrict__ Ww, const float* __restrict__ Wb,
                                 float* __restrict__ out) {
    int wid  = (blockIdx.x * blockDim.x + threadIdx.x) >> 5;
    int lane = threadIdx.x & 31;
    if (wid >= N_NODES) return;
    int n = wid;
    const float4* H = (const float4*)(g_acc + (size_t)n * J_DIM);
    float4 v[4][2];
    #pragma unroll
    for (int ch = 0; ch < 4; ch++) {
        v[ch][0] = H[ch * 64 + lane];
        v[ch][1] = H[ch * 64 + lane + 32];
    }
    float dl[2], wl[2];
    #pragma unroll
    for (int r = 0; r < 2; r++) {
        const float4* DwR = (const float4*)(Dw + r * 512);
        const float4* WwR = (const float4*)(Ww + r * 512);
        float4 d0 = DwR[lane], d1 = DwR[lane+32], d2 = DwR[64+lane], d3 = DwR[64+lane+32];
        float4 w0 = WwR[lane], w1 = WwR[lane+32], w2 = WwR[64+lane], w3 = WwR[64+lane+32];
        float sD = v[0][0].x*d0.x + v[0][0].y*d0.y + v[0][0].z*d0.z + v[0][0].w*d0.w
                 + v[0][1].x*d1.x + v[0][1].y*d1.y + v[0][1].z*d1.z + v[0][1].w*d1.w
                 + v[1][0].x*d2.x + v[1][0].y*d2.y + v[1][0].z*d2.z + v[1][0].w*d2.w
                 + v[1][1].x*d3.x + v[1][1].y*d3.y + v[1][1].z*d3.z + v[1][1].w*d3.w;
        float sW = v[2][0].x*w0.x + v[2][0].y*w0.y + v[2][0].z*w0.z + v[2][0].w*w0.w
                 + v[2][1].x*w1.x + v[2][1].y*w1.y + v[2][1].z*w1.z + v[2][1].w*w1.w
                 + v[3][0].x*w2.x + v[3][0].y*w2.y + v[3][0].z*w2.z + v[3][0].w*w2.w
                 + v[3][1].x*w3.x + v[3][1].y*w3.y + v[3][1].z*w3.z + v[3][1].w*w3.w;
        dl[r] = warpsum(sD) + __ldg(&Db[r]);
        wl[r] = warpsum(sW) + __ldg(&Wb[r]);
    }
    float mD = fmaxf(dl[0], dl[1]);
    float e0 = __expf(dl[0] - mD), e1 = __expf(dl[1] - mD);
    float a0 = e0 / (e0 + e1), a1 = e1 / (e0 + e1);
    float mW = fmaxf(wl[0], wl[1]);
    float f0 = __expf(wl[0] - mW), f1 = __expf(wl[1] - mW);
    float b0 = f0 / (f0 + f1), b1 = f1 / (f0 + f1);

    int mode = g_mask_mode;
    bool msk;
    if (mode == 1)      msk = ((const int*)tm)[n] != 0;
    else if (mode == 2) msk = ((const float*)tm)[n] != 0.f;
    else                msk = ((const unsigned char*)tm)[n] != 0;

    float4 r0, r1;
    if (msk) {
        r0.x = v[2][0].x*b0 + v[3][0].x*b1; r0.y = v[2][0].y*b0 + v[3][0].y*b1;
        r0.z = v[2][0].z*b0 + v[3][0].z*b1; r0.w = v[2][0].w*b0 + v[3][0].w*b1;
        r1.x = v[2][1].x*b0 + v[3][1].x*b1; r1.y = v[2][1].y*b0 + v[3][1].y*b1;
        r1.z = v[2][1].z*b0 + v[3][1].z*b1; r1.w = v[2][1].w*b0 + v[3][1].w*b1;
    } else {
        r0.x = v[0][0].x*a0 + v[1][0].x*a1; r0.y = v[0][0].y*a0 + v[1][0].y*a1;
        r0.z = v[0][0].z*a0 + v[1][0].z*a1; r0.w = v[0][0].w*a0 + v[1][0].w*a1;
        r1.x = v[0][1].x*a0 + v[1][1].x*a1; r1.y = v[0][1].y*a0 + v[1][1].y*a1;
        r1.z = v[0][1].z*a0 + v[1][1].z*a1; r1.w = v[0][1].w*a0 + v[1][1].w*a1;
    }
    float4* o4 = (float4*)(out + (size_t)n * 256);
    o4[lane]      = r0;
    o4[lane + 32] = r1;
}

// ---------------- launch ---------------------------------------------------------
extern "C" void kernel_launch(void* const* d_in, const int* in_sizes, int n_in,
                              void* d_out, int out_size) {
    const float* feature = (const float*)d_in[0];
    const int*   src     = (const int*)  d_in[1];
    const int*   dst     = (const int*)  d_in[2];
    const void*  tmask   =               d_in[3];
    const float* Wl      = (const float*)d_in[4];
    const float* a_src   = (const float*)d_in[5];
    const float* a_dst   = (const float*)d_in[6];
    const float* bias    = (const float*)d_in[7];
    const float* Dw      = (const float*)d_in[8];
    const float* Db      = (const float*)d_in[9];
    const float* Ww      = (const float*)d_in[10];
    const float* Wb      = (const float*)d_in[11];
    float* out = (float*)d_out;

    cudaFuncSetAttribute(mma_gemm_kernel, cudaFuncAttributeMaxDynamicSharedMemorySize, SM_GEMM);

    detect_kernel<<<1, 256>>>((const unsigned char*)tmask);
    init_kernel<<<3125, 256>>>();
    split_kernel<<<50000, 256>>>(feature, Wl);
    mma_gemm_kernel<<<dim3(4, 391), 256, SM_GEMM>>>(a_src, a_dst);
    edge_max_kernel<<<12500, 256>>>(src, dst);
    scan1_kernel<<<SCAN_BLOCKS, 1024>>>();
    scan2_kernel<<<1, 256>>>();
    scan3_kernel<<<SCAN_BLOCKS, 1024>>>();
    expsum_permute_kernel<<<12500, 256>>>(src, dst);
    gather_kernel<<<25000, 256>>>(bias);
    aggregate_kernel<<<6250, 256>>>(tmask, Dw, Db, Ww, Wb, out);
}